// round 3
// baseline (speedup 1.0000x reference)
#include <cuda_runtime.h>
#include <math.h>
#include <stddef.h>

// Problem shape (fixed)
#define BB 4
#define SS 2048
#define DD 1024
#define HH 16
#define HD 64
#define MM (BB * SS)   // 8192 rows for all projection GEMMs

// ---------------------------------------------------------------------------
// Scratch: __device__ globals (no runtime allocation allowed).
// Q/K/V projections and attention output, each [B,S,D] fp32 = 32 MB.
// ---------------------------------------------------------------------------
__device__ float g_Q[MM * DD];
__device__ float g_K[MM * DD];
__device__ float g_V[MM * DD];
__device__ float g_X[MM * DD];

// ---------------------------------------------------------------------------
// GEMM: C[M,N] = A[M,K] * W[N,K]^T + bias[N]   (both operands K-major -> NT)
// 128x128 block tile, BK=8, 256 threads, 8x8 per-thread micro-tile.
// Double-buffered SMEM: global loads for tile k+1 overlap FFMA on tile k.
// M=8192, N=1024, K=1024 -> all tile dims divide exactly, no bounds checks.
// ---------------------------------------------------------------------------
__global__ void __launch_bounds__(256, 2) gemm_nt_bias(
    const float* __restrict__ A, const float* __restrict__ W,
    const float* __restrict__ bias, float* __restrict__ C,
    int M, int N, int K)
{
    const int BM = 128, BN = 128, BK = 8;
    __shared__ float As[2][BK][BM];
    __shared__ float Bs[2][BK][BN];

    const int tid = threadIdx.x;
    const int tx  = tid & 15;   // 0..15  -> N direction
    const int ty  = tid >> 4;   // 0..15  -> M direction

    const int row0 = blockIdx.y * BM;
    const int col0 = blockIdx.x * BN;

    const float* Ap = A + (size_t)row0 * K;
    const float* Wp = W + (size_t)col0 * K;

    float acc[8][8];
#pragma unroll
    for (int i = 0; i < 8; i++)
#pragma unroll
        for (int j = 0; j < 8; j++) acc[i][j] = 0.0f;

    // Each thread loads one float4 of A-tile and one of W-tile per k-step.
    const int lr = tid >> 1;         // 0..127 (tile row)
    const int lc = (tid & 1) * 4;    // 0 or 4 (k offset)

    // Prologue: load tile 0 into buffer 0.
    {
        float4 a4 = *(const float4*)(Ap + (size_t)lr * K + lc);
        float4 b4 = *(const float4*)(Wp + (size_t)lr * K + lc);
        As[0][lc + 0][lr] = a4.x; As[0][lc + 1][lr] = a4.y;
        As[0][lc + 2][lr] = a4.z; As[0][lc + 3][lr] = a4.w;
        Bs[0][lc + 0][lr] = b4.x; Bs[0][lc + 1][lr] = b4.y;
        Bs[0][lc + 2][lr] = b4.z; Bs[0][lc + 3][lr] = b4.w;
    }
    __syncthreads();

    int buf = 0;
    for (int k0 = 0; k0 < K; k0 += BK) {
        // Issue next tile's global loads early (latency overlapped w/ FFMA).
        float4 a4, b4;
        const bool more = (k0 + BK) < K;
        if (more) {
            a4 = *(const float4*)(Ap + (size_t)lr * K + k0 + BK + lc);
            b4 = *(const float4*)(Wp + (size_t)lr * K + k0 + BK + lc);
        }

#pragma unroll
        for (int kk = 0; kk < BK; kk++) {
            float ra[8], rb[8];
            float4 t;
            t = *(const float4*)&As[buf][kk][ty * 8];     ra[0]=t.x; ra[1]=t.y; ra[2]=t.z; ra[3]=t.w;
            t = *(const float4*)&As[buf][kk][ty * 8 + 4]; ra[4]=t.x; ra[5]=t.y; ra[6]=t.z; ra[7]=t.w;
            t = *(const float4*)&Bs[buf][kk][tx * 8];     rb[0]=t.x; rb[1]=t.y; rb[2]=t.z; rb[3]=t.w;
            t = *(const float4*)&Bs[buf][kk][tx * 8 + 4]; rb[4]=t.x; rb[5]=t.y; rb[6]=t.z; rb[7]=t.w;
#pragma unroll
            for (int i = 0; i < 8; i++)
#pragma unroll
                for (int j = 0; j < 8; j++)
                    acc[i][j] = fmaf(ra[i], rb[j], acc[i][j]);
        }

        if (more) {
            const int nb = buf ^ 1;
            As[nb][lc + 0][lr] = a4.x; As[nb][lc + 1][lr] = a4.y;
            As[nb][lc + 2][lr] = a4.z; As[nb][lc + 3][lr] = a4.w;
            Bs[nb][lc + 0][lr] = b4.x; Bs[nb][lc + 1][lr] = b4.y;
            Bs[nb][lc + 2][lr] = b4.z; Bs[nb][lc + 3][lr] = b4.w;
        }
        __syncthreads();
        buf ^= 1;
    }

#pragma unroll
    for (int i = 0; i < 8; i++) {
        const int r = row0 + ty * 8 + i;
        float* Crow = C + (size_t)r * N + col0 + tx * 8;
#pragma unroll
        for (int j = 0; j < 8; j++)
            Crow[j] = acc[i][j] + bias[col0 + tx * 8 + j];
    }
}

// ---------------------------------------------------------------------------
// Flash attention (fp32, online softmax). One block = one (b, h, 64-query tile).
// 256 threads as 16x16: thread (ty,tx) owns 4 query rows (ty*4+ii) and,
// for scores, 2 key cols (tx*2+jj); for the PV product, 4 head dims (tx*4+dd).
// Row-wise max/sum reductions run over the 16 tx lanes via shfl (half-warp:
// all 16 lanes of a half-warp share the same ty).
// scale = 1/sqrt(D) = 1/32 (module scales by hid_dim, not head_dim).
// ---------------------------------------------------------------------------
#define BQ 64
#define BKV 32

__global__ void __launch_bounds__(256, 4) flash_attn(
    const float* __restrict__ Q, const float* __restrict__ K,
    const float* __restrict__ V, float* __restrict__ O)
{
    __shared__ float Qs[BQ][HD + 1];     // 64x65
    __shared__ float Ks[BKV][HD + 1];    // 32x65
    __shared__ float Vs[BKV][HD + 1];    // 32x65
    __shared__ float Ps[BQ][BKV + 1];    // 64x33

    const int b  = blockIdx.z;
    const int h  = blockIdx.y;
    const int q0 = blockIdx.x * BQ;

    const int tid = threadIdx.x;
    const int tx  = tid & 15;
    const int ty  = tid >> 4;

    const size_t headOff = (size_t)h * HD;
    const size_t baseQ = ((size_t)b * SS + q0) * DD + headOff;

    // Load Q tile: 64x64 floats = 1024 float4, 4 per thread.
    for (int i = tid; i < BQ * (HD / 4); i += 256) {
        const int r  = i >> 4;
        const int c4 = (i & 15) * 4;
        float4 v = *(const float4*)(Q + baseQ + (size_t)r * DD + c4);
        Qs[r][c4] = v.x; Qs[r][c4 + 1] = v.y; Qs[r][c4 + 2] = v.z; Qs[r][c4 + 3] = v.w;
    }

    float m_i[4], l_i[4], acc[4][4];
#pragma unroll
    for (int ii = 0; ii < 4; ii++) {
        m_i[ii] = -1e30f; l_i[ii] = 0.0f;
#pragma unroll
        for (int dd = 0; dd < 4; dd++) acc[ii][dd] = 0.0f;
    }
    const float scale = 0.03125f;  // 1/32

    for (int k0 = 0; k0 < SS; k0 += BKV) {
        __syncthreads();   // previous tile's Ks/Vs/Ps reads done
        const size_t baseK = ((size_t)b * SS + k0) * DD + headOff;
        // Load K/V tiles: 32x64 each = 512 float4; each thread does 2 of each.
        for (int i = tid; i < BKV * (HD / 4); i += 256) {
            const int r  = i >> 4;
            const int c4 = (i & 15) * 4;
            float4 kv = *(const float4*)(K + baseK + (size_t)r * DD + c4);
            Ks[r][c4] = kv.x; Ks[r][c4 + 1] = kv.y; Ks[r][c4 + 2] = kv.z; Ks[r][c4 + 3] = kv.w;
            float4 vv = *(const float4*)(V + baseK + (size_t)r * DD + c4);
            Vs[r][c4] = vv.x; Vs[r][c4 + 1] = vv.y; Vs[r][c4 + 2] = vv.z; Vs[r][c4 + 3] = vv.w;
        }
        __syncthreads();

        // Scores: s[ii][jj] = Q[ty*4+ii] . K[tx*2+jj]
        float s[4][2] = {{0.f,0.f},{0.f,0.f},{0.f,0.f},{0.f,0.f}};
#pragma unroll 16
        for (int d = 0; d < HD; d++) {
            float qa[4], kb[2];
#pragma unroll
            for (int ii = 0; ii < 4; ii++) qa[ii] = Qs[ty * 4 + ii][d];
#pragma unroll
            for (int jj = 0; jj < 2; jj++) kb[jj] = Ks[tx * 2 + jj][d];
#pragma unroll
            for (int ii = 0; ii < 4; ii++)
#pragma unroll
                for (int jj = 0; jj < 2; jj++)
                    s[ii][jj] = fmaf(qa[ii], kb[jj], s[ii][jj]);
        }

        // Online softmax per query row (reduce across 16 tx lanes)
#pragma unroll
        for (int ii = 0; ii < 4; ii++) {
            float s0 = s[ii][0] * scale;
            float s1 = s[ii][1] * scale;
            float rmax = fmaxf(s0, s1);
#pragma unroll
            for (int o = 8; o >= 1; o >>= 1)
                rmax = fmaxf(rmax, __shfl_xor_sync(0xffffffffu, rmax, o));
            const float mnew = fmaxf(m_i[ii], rmax);
            const float corr = __expf(m_i[ii] - mnew);
            const float p0 = __expf(s0 - mnew);
            const float p1 = __expf(s1 - mnew);
            Ps[ty * 4 + ii][tx * 2]     = p0;
            Ps[ty * 4 + ii][tx * 2 + 1] = p1;
            float rsum = p0 + p1;
#pragma unroll
            for (int o = 8; o >= 1; o >>= 1)
                rsum += __shfl_xor_sync(0xffffffffu, rsum, o);
            l_i[ii] = l_i[ii] * corr + rsum;
            m_i[ii] = mnew;
#pragma unroll
            for (int dd = 0; dd < 4; dd++) acc[ii][dd] *= corr;
        }
        __syncwarp();   // Ps produced & consumed by the same half-warp

        // acc += P * V : thread owns dims tx*4+dd
#pragma unroll 8
        for (int j = 0; j < BKV; j++) {
            float vv[4];
#pragma unroll
            for (int dd = 0; dd < 4; dd++) vv[dd] = Vs[j][tx * 4 + dd];
#pragma unroll
            for (int ii = 0; ii < 4; ii++) {
                const float p = Ps[ty * 4 + ii][j];
#pragma unroll
                for (int dd = 0; dd < 4; dd++)
                    acc[ii][dd] = fmaf(p, vv[dd], acc[ii][dd]);
            }
        }
    }

    // Write normalized output back in [B,S,D] layout (heads re-interleaved)
#pragma unroll
    for (int ii = 0; ii < 4; ii++) {
        const float inv = 1.0f / l_i[ii];
        const size_t outBase = ((size_t)b * SS + q0 + ty * 4 + ii) * DD + headOff + tx * 4;
#pragma unroll
        for (int dd = 0; dd < 4; dd++)
            O[outBase + dd] = acc[ii][dd] * inv;
    }
}

// ---------------------------------------------------------------------------
// Launch: 3 projection GEMMs -> flash attention -> output GEMM.
// Graph-capturable: kernel launches only, deterministic, no allocation.
// ---------------------------------------------------------------------------
extern "C" void kernel_launch(void* const* d_in, const int* in_sizes, int n_in,
                              void* d_out, int out_size)
{
    const float* query = (const float*)d_in[0];
    const float* key   = (const float*)d_in[1];
    const float* value = (const float*)d_in[2];
    const float* Wq    = (const float*)d_in[3];
    const float* bq    = (const float*)d_in[4];
    const float* Wk    = (const float*)d_in[5];
    const float* bk    = (const float*)d_in[6];
    const float* Wv    = (const float*)d_in[7];
    const float* bv    = (const float*)d_in[8];
    const float* Wo    = (const float*)d_in[9];
    const float* bo    = (const float*)d_in[10];
    float* out = (float*)d_out;

    float *gq, *gk, *gv, *gx;
    cudaGetSymbolAddress((void**)&gq, g_Q);
    cudaGetSymbolAddress((void**)&gk, g_K);
    cudaGetSymbolAddress((void**)&gv, g_V);
    cudaGetSymbolAddress((void**)&gx, g_X);

    dim3 gemmGrid(DD / 128, MM / 128);   // (8, 64)
    gemm_nt_bias<<<gemmGrid, 256>>>(query, Wq, bq, gq, MM, DD, DD);
    gemm_nt_bias<<<gemmGrid, 256>>>(key,   Wk, bk, gk, MM, DD, DD);
    gemm_nt_bias<<<gemmGrid, 256>>>(value, Wv, bv, gv, MM, DD, DD);

    dim3 attnGrid(SS / BQ, HH, BB);      // (32, 16, 4)
    flash_attn<<<attnGrid, 256>>>(gq, gk, gv, gx);

    dim3 oGrid(DD / 128, MM / 128);
    gemm_nt_bias<<<oGrid, 256>>>(gx, Wo, bo, out, MM, DD, DD);
}

// round 6
// speedup vs baseline: 1.4329x; 1.4329x over previous
#include <cuda_runtime.h>
#include <cstdint>
#include <math.h>
#include <stddef.h>

// Problem shape (fixed)
#define BB 4
#define SS 2048
#define DD 1024
#define HH 16
#define HD 64
#define MM (BB * SS)   // 8192 rows for all projection GEMMs

// ---------------------------------------------------------------------------
// Scratch (__device__ globals; no runtime allocation allowed)
// ---------------------------------------------------------------------------
__device__ float g_Q[MM * DD];
__device__ float g_K[MM * DD];
__device__ float g_V[MM * DD];
__device__ float g_X[MM * DD];

// ---------------------------------------------------------------------------
// tf32 helpers
// ---------------------------------------------------------------------------
__device__ __forceinline__ uint32_t f2tf32(float x) {
    uint32_t r;
    asm("cvt.rna.tf32.f32 %0, %1;" : "=r"(r) : "f"(x));
    return r;
}
__device__ __forceinline__ float tf32f(float x) {
    return __uint_as_float(f2tf32(x));
}
__device__ __forceinline__ void mma_tf32(float c[4],
    uint32_t a0, uint32_t a1, uint32_t a2, uint32_t a3,
    uint32_t b0, uint32_t b1)
{
    asm volatile(
        "mma.sync.aligned.m16n8k8.row.col.f32.tf32.tf32.f32 "
        "{%0,%1,%2,%3}, {%4,%5,%6,%7}, {%8,%9}, {%0,%1,%2,%3};"
        : "+f"(c[0]), "+f"(c[1]), "+f"(c[2]), "+f"(c[3])
        : "r"(a0), "r"(a1), "r"(a2), "r"(a3), "r"(b0), "r"(b1));
}
__device__ __forceinline__ uint32_t fbits(float x) { return __float_as_uint(x); }

// ---------------------------------------------------------------------------
// GEMM (3xTF32): C[M,N] = A[M,K] * W[N,K]^T + bias[N],  K = N = 1024 fixed.
// 128x128 block tile, BK=16, 256 threads (8 warps: 2 x 4 warp grid,
// warp tile 64x32 = 4 m16 x 4 n8 mma tiles). SMEM single-buffered with
// register prefetch of the next k-slab. Split A = Ah + Al, W = Bh + Bl
// (tf32 rounding) and accumulate Ah*Bh + Ah*Bl + Al*Bh in fp32.
// ---------------------------------------------------------------------------
#define GBK 16
#define GAS 136   // SMEM row stride: 136 % 32 == 8 -> conflict-free frag loads

__global__ void __launch_bounds__(256, 2) gemm_tf32_nt_bias(
    const float* __restrict__ A, const float* __restrict__ W,
    const float* __restrict__ bias, float* __restrict__ C)
{
    __shared__ float Ah[GBK][GAS], Al[GBK][GAS];
    __shared__ float Bh[GBK][GAS], Bl[GBK][GAS];

    const int tid  = threadIdx.x;
    const int lane = tid & 31;
    const int wid  = tid >> 5;
    const int r    = lane >> 2;   // 0..7
    const int cl   = lane & 3;    // 0..3
    const int wm   = (wid & 1) * 64;
    const int wn   = (wid >> 1) * 32;

    const int row0 = blockIdx.y * 128;
    const int col0 = blockIdx.x * 128;

    // Loader mapping: 512 float4 per operand per k-slab; 2 per thread.
    // f4 index i: row = i>>2 (0..127), kc = (i&3)*4 (0..12)
    const int li0 = tid, li1 = tid + 256;
    const int lr0 = li0 >> 2, lkc0 = (li0 & 3) * 4;
    const int lr1 = li1 >> 2, lkc1 = (li1 & 3) * 4;

    float c[4][4][4];
#pragma unroll
    for (int mt = 0; mt < 4; mt++)
#pragma unroll
        for (int nt = 0; nt < 4; nt++)
#pragma unroll
            for (int q = 0; q < 4; q++) c[mt][nt][q] = 0.0f;

    float4 pa0, pa1, pb0, pb1;
    // Prologue: load k-slab 0
    pa0 = *(const float4*)(A + (size_t)(row0 + lr0) * 1024 + lkc0);
    pa1 = *(const float4*)(A + (size_t)(row0 + lr1) * 1024 + lkc1);
    pb0 = *(const float4*)(W + (size_t)(col0 + lr0) * 1024 + lkc0);
    pb1 = *(const float4*)(W + (size_t)(col0 + lr1) * 1024 + lkc1);

    for (int k0 = 0; k0 < 1024; k0 += GBK) {
        // split + store current slab to SMEM
        {
            const float av0[4] = {pa0.x, pa0.y, pa0.z, pa0.w};
            const float av1[4] = {pa1.x, pa1.y, pa1.z, pa1.w};
            const float bv0[4] = {pb0.x, pb0.y, pb0.z, pb0.w};
            const float bv1[4] = {pb1.x, pb1.y, pb1.z, pb1.w};
#pragma unroll
            for (int j = 0; j < 4; j++) {
                float h;
                h = tf32f(av0[j]); Ah[lkc0 + j][lr0] = h; Al[lkc0 + j][lr0] = tf32f(av0[j] - h);
                h = tf32f(av1[j]); Ah[lkc1 + j][lr1] = h; Al[lkc1 + j][lr1] = tf32f(av1[j] - h);
                h = tf32f(bv0[j]); Bh[lkc0 + j][lr0] = h; Bl[lkc0 + j][lr0] = tf32f(bv0[j] - h);
                h = tf32f(bv1[j]); Bh[lkc1 + j][lr1] = h; Bl[lkc1 + j][lr1] = tf32f(bv1[j] - h);
            }
        }
        __syncthreads();

        // prefetch next slab
        const bool more = (k0 + GBK) < 1024;
        if (more) {
            const int kn = k0 + GBK;
            pa0 = *(const float4*)(A + (size_t)(row0 + lr0) * 1024 + kn + lkc0);
            pa1 = *(const float4*)(A + (size_t)(row0 + lr1) * 1024 + kn + lkc1);
            pb0 = *(const float4*)(W + (size_t)(col0 + lr0) * 1024 + kn + lkc0);
            pb1 = *(const float4*)(W + (size_t)(col0 + lr1) * 1024 + kn + lkc1);
        }

#pragma unroll
        for (int kk8 = 0; kk8 < 2; kk8++) {
            const int kb = kk8 * 8;
            uint32_t bh0[4], bh1[4], bl0[4], bl1[4];
#pragma unroll
            for (int nt = 0; nt < 4; nt++) {
                const int n = wn + nt * 8 + r;
                bh0[nt] = fbits(Bh[kb + cl][n]);
                bh1[nt] = fbits(Bh[kb + cl + 4][n]);
                bl0[nt] = fbits(Bl[kb + cl][n]);
                bl1[nt] = fbits(Bl[kb + cl + 4][n]);
            }
#pragma unroll
            for (int mt = 0; mt < 4; mt++) {
                const int mrow = wm + mt * 16 + r;
                const uint32_t ah0 = fbits(Ah[kb + cl][mrow]);
                const uint32_t ah1 = fbits(Ah[kb + cl][mrow + 8]);
                const uint32_t ah2 = fbits(Ah[kb + cl + 4][mrow]);
                const uint32_t ah3 = fbits(Ah[kb + cl + 4][mrow + 8]);
                const uint32_t al0 = fbits(Al[kb + cl][mrow]);
                const uint32_t al1 = fbits(Al[kb + cl][mrow + 8]);
                const uint32_t al2 = fbits(Al[kb + cl + 4][mrow]);
                const uint32_t al3 = fbits(Al[kb + cl + 4][mrow + 8]);
#pragma unroll
                for (int nt = 0; nt < 4; nt++) {
                    mma_tf32(c[mt][nt], ah0, ah1, ah2, ah3, bh0[nt], bh1[nt]);
                    mma_tf32(c[mt][nt], ah0, ah1, ah2, ah3, bl0[nt], bl1[nt]);
                    mma_tf32(c[mt][nt], al0, al1, al2, al3, bh0[nt], bh1[nt]);
                }
            }
        }
        __syncthreads();
    }

    // Epilogue: add bias, write fp32
#pragma unroll
    for (int mt = 0; mt < 4; mt++) {
        const int gr0 = row0 + wm + mt * 16 + r;
        const int gr1 = gr0 + 8;
#pragma unroll
        for (int nt = 0; nt < 4; nt++) {
            const int gc = col0 + wn + nt * 8 + 2 * cl;
            const float b0 = __ldg(bias + gc);
            const float b1 = __ldg(bias + gc + 1);
            float2 v0 = {c[mt][nt][0] + b0, c[mt][nt][1] + b1};
            float2 v1 = {c[mt][nt][2] + b0, c[mt][nt][3] + b1};
            *(float2*)(C + (size_t)gr0 * 1024 + gc) = v0;
            *(float2*)(C + (size_t)gr1 * 1024 + gc) = v1;
        }
    }
}

// ---------------------------------------------------------------------------
// Flash attention, tensor-core tf32.
// Block = (b, h, 64-query tile); 128 threads = 4 warps; warp owns 16 q rows.
// KV tile = 32 keys. QK^T: 1xTF32 (scale 1/32 folded into Q, exact pow2).
// PV: 3-term split (Ph*Vh + Ph*Vl + Pl*Vh) -> ~fp32 accuracy.
// SMEM strides chosen for conflict-free fragment loads.
// ---------------------------------------------------------------------------
#define FBQ 64
#define FBKV 32

__global__ void __launch_bounds__(128, 4) flash_tf32(
    const float* __restrict__ Q, const float* __restrict__ K,
    const float* __restrict__ V, float* __restrict__ O)
{
    __shared__ float Ksm[FBKV][68];          // keys x dims (hi only)
    __shared__ float Vh[FBKV][68], Vl[FBKV][68];
    __shared__ float Ph[FBQ][36], Pl[FBQ][36];

    const int b  = blockIdx.z;
    const int h  = blockIdx.y;
    const int q0 = blockIdx.x * FBQ;

    const int tid  = threadIdx.x;
    const int lane = tid & 31;
    const int wid  = tid >> 5;
    const int r    = lane >> 2;
    const int cl   = lane & 3;
    const int qw   = wid * 16;

    // ---- Q fragments, pre-scaled by 1/32, tf32-rounded, held in registers
    uint32_t qa[8][4];
    {
        const size_t base = ((size_t)(b * SS + q0 + qw + r)) * DD + (size_t)h * HD;
#pragma unroll
        for (int c = 0; c < 8; c++) {
            const size_t p0 = base + c * 8 + cl;
            qa[c][0] = f2tf32(Q[p0] * 0.03125f);
            qa[c][1] = f2tf32(Q[p0 + (size_t)8 * DD] * 0.03125f);
            qa[c][2] = f2tf32(Q[p0 + 4] * 0.03125f);
            qa[c][3] = f2tf32(Q[p0 + (size_t)8 * DD + 4] * 0.03125f);
        }
    }

    float o[8][4];
#pragma unroll
    for (int dn = 0; dn < 8; dn++)
#pragma unroll
        for (int q = 0; q < 4; q++) o[dn][q] = 0.0f;
    float m0 = -1e30f, m1 = -1e30f, l0 = 0.0f, l1 = 0.0f;

    for (int kv = 0; kv < SS; kv += FBKV) {
        __syncthreads();   // prior tile fully consumed
        // ---- load K/V tile (split V) ----
        for (int i = tid; i < FBKV * (HD / 4); i += 128) {   // 512 float4
            const int key = i >> 4;
            const int c4  = (i & 15) * 4;
            const size_t g = ((size_t)(b * SS + kv + key)) * DD + (size_t)h * HD + c4;
            float4 kk = *(const float4*)(K + g);
            Ksm[key][c4 + 0] = tf32f(kk.x);
            Ksm[key][c4 + 1] = tf32f(kk.y);
            Ksm[key][c4 + 2] = tf32f(kk.z);
            Ksm[key][c4 + 3] = tf32f(kk.w);
            float4 vv = *(const float4*)(V + g);
            const float va[4] = {vv.x, vv.y, vv.z, vv.w};
#pragma unroll
            for (int j = 0; j < 4; j++) {
                const float hi = tf32f(va[j]);
                Vh[key][c4 + j] = hi;
                Vl[key][c4 + j] = tf32f(va[j] - hi);
            }
        }
        __syncthreads();

        // ---- S = Q K^T (scaled) ----
        float s[4][4];
#pragma unroll
        for (int nt = 0; nt < 4; nt++)
#pragma unroll
            for (int q = 0; q < 4; q++) s[nt][q] = 0.0f;
#pragma unroll
        for (int c = 0; c < 8; c++) {
            uint32_t kb0[4], kb1[4];
#pragma unroll
            for (int nt = 0; nt < 4; nt++) {
                kb0[nt] = fbits(Ksm[nt * 8 + r][c * 8 + cl]);
                kb1[nt] = fbits(Ksm[nt * 8 + r][c * 8 + cl + 4]);
            }
#pragma unroll
            for (int nt = 0; nt < 4; nt++)
                mma_tf32(s[nt], qa[c][0], qa[c][1], qa[c][2], qa[c][3], kb0[nt], kb1[nt]);
        }

        // ---- online softmax; store split P to SMEM ----
        // row 0 (frag regs 0,1), row 1 (frag regs 2,3)
        {
            float tm = fmaxf(fmaxf(s[0][0], s[0][1]), fmaxf(s[1][0], s[1][1]));
            tm = fmaxf(tm, fmaxf(fmaxf(s[2][0], s[2][1]), fmaxf(s[3][0], s[3][1])));
            tm = fmaxf(tm, __shfl_xor_sync(0xffffffffu, tm, 1));
            tm = fmaxf(tm, __shfl_xor_sync(0xffffffffu, tm, 2));
            const float mnew = fmaxf(m0, tm);
            const float corr = __expf(m0 - mnew);
            m0 = mnew;
            float rs = 0.0f;
#pragma unroll
            for (int nt = 0; nt < 4; nt++) {
                const float p0 = __expf(s[nt][0] - mnew);
                const float p1 = __expf(s[nt][1] - mnew);
                rs += p0 + p1;
                const float h0 = tf32f(p0), h1 = tf32f(p1);
                float2 ph = {h0, h1};
                float2 pl = {tf32f(p0 - h0), tf32f(p1 - h1)};
                *(float2*)&Ph[qw + r][nt * 8 + 2 * cl] = ph;
                *(float2*)&Pl[qw + r][nt * 8 + 2 * cl] = pl;
            }
            rs += __shfl_xor_sync(0xffffffffu, rs, 1);
            rs += __shfl_xor_sync(0xffffffffu, rs, 2);
            l0 = l0 * corr + rs;
#pragma unroll
            for (int dn = 0; dn < 8; dn++) { o[dn][0] *= corr; o[dn][1] *= corr; }
        }
        {
            float tm = fmaxf(fmaxf(s[0][2], s[0][3]), fmaxf(s[1][2], s[1][3]));
            tm = fmaxf(tm, fmaxf(fmaxf(s[2][2], s[2][3]), fmaxf(s[3][2], s[3][3])));
            tm = fmaxf(tm, __shfl_xor_sync(0xffffffffu, tm, 1));
            tm = fmaxf(tm, __shfl_xor_sync(0xffffffffu, tm, 2));
            const float mnew = fmaxf(m1, tm);
            const float corr = __expf(m1 - mnew);
            m1 = mnew;
            float rs = 0.0f;
#pragma unroll
            for (int nt = 0; nt < 4; nt++) {
                const float p0 = __expf(s[nt][2] - mnew);
                const float p1 = __expf(s[nt][3] - mnew);
                rs += p0 + p1;
                const float h0 = tf32f(p0), h1 = tf32f(p1);
                float2 ph = {h0, h1};
                float2 pl = {tf32f(p0 - h0), tf32f(p1 - h1)};
                *(float2*)&Ph[qw + r + 8][nt * 8 + 2 * cl] = ph;
                *(float2*)&Pl[qw + r + 8][nt * 8 + 2 * cl] = pl;
            }
            rs += __shfl_xor_sync(0xffffffffu, rs, 1);
            rs += __shfl_xor_sync(0xffffffffu, rs, 2);
            l1 = l1 * corr + rs;
#pragma unroll
            for (int dn = 0; dn < 8; dn++) { o[dn][2] *= corr; o[dn][3] *= corr; }
        }
        __syncwarp();   // P rows are warp-private: produce -> consume in-warp

        // ---- O += P V (3-term split) ----
#pragma unroll
        for (int kc = 0; kc < 4; kc++) {
            const uint32_t pah0 = fbits(Ph[qw + r][kc * 8 + cl]);
            const uint32_t pah1 = fbits(Ph[qw + r + 8][kc * 8 + cl]);
            const uint32_t pah2 = fbits(Ph[qw + r][kc * 8 + cl + 4]);
            const uint32_t pah3 = fbits(Ph[qw + r + 8][kc * 8 + cl + 4]);
            const uint32_t pal0 = fbits(Pl[qw + r][kc * 8 + cl]);
            const uint32_t pal1 = fbits(Pl[qw + r + 8][kc * 8 + cl]);
            const uint32_t pal2 = fbits(Pl[qw + r][kc * 8 + cl + 4]);
            const uint32_t pal3 = fbits(Pl[qw + r + 8][kc * 8 + cl + 4]);
#pragma unroll
            for (int dn = 0; dn < 8; dn++) {
                const uint32_t vb0h = fbits(Vh[kc * 8 + cl][dn * 8 + r]);
                const uint32_t vb1h = fbits(Vh[kc * 8 + cl + 4][dn * 8 + r]);
                const uint32_t vb0l = fbits(Vl[kc * 8 + cl][dn * 8 + r]);
                const uint32_t vb1l = fbits(Vl[kc * 8 + cl + 4][dn * 8 + r]);
                mma_tf32(o[dn], pah0, pah1, pah2, pah3, vb0h, vb1h);
                mma_tf32(o[dn], pah0, pah1, pah2, pah3, vb0l, vb1l);
                mma_tf32(o[dn], pal0, pal1, pal2, pal3, vb0h, vb1h);
            }
        }
    }

    // ---- epilogue: normalize, write [B,S,D] with heads re-interleaved ----
    const float inv0 = 1.0f / l0;
    const float inv1 = 1.0f / l1;
    const size_t ob0 = ((size_t)(b * SS + q0 + qw + r)) * DD + (size_t)h * HD;
    const size_t ob1 = ob0 + (size_t)8 * DD;
#pragma unroll
    for (int dn = 0; dn < 8; dn++) {
        const int gc = dn * 8 + 2 * cl;
        float2 v0 = {o[dn][0] * inv0, o[dn][1] * inv0};
        float2 v1 = {o[dn][2] * inv1, o[dn][3] * inv1};
        *(float2*)(O + ob0 + gc) = v0;
        *(float2*)(O + ob1 + gc) = v1;
    }
}

// ---------------------------------------------------------------------------
// Launch: 3 projection GEMMs -> flash attention -> output GEMM.
// Graph-capturable: kernel launches only, deterministic, no allocation.
// ---------------------------------------------------------------------------
extern "C" void kernel_launch(void* const* d_in, const int* in_sizes, int n_in,
                              void* d_out, int out_size)
{
    const float* query = (const float*)d_in[0];
    const float* key   = (const float*)d_in[1];
    const float* value = (const float*)d_in[2];
    const float* Wq    = (const float*)d_in[3];
    const float* bq    = (const float*)d_in[4];
    const float* Wk    = (const float*)d_in[5];
    const float* bk    = (const float*)d_in[6];
    const float* Wv    = (const float*)d_in[7];
    const float* bv    = (const float*)d_in[8];
    const float* Wo    = (const float*)d_in[9];
    const float* bo    = (const float*)d_in[10];
    float* out = (float*)d_out;

    float *gq, *gk, *gv, *gx;
    cudaGetSymbolAddress((void**)&gq, g_Q);
    cudaGetSymbolAddress((void**)&gk, g_K);
    cudaGetSymbolAddress((void**)&gv, g_V);
    cudaGetSymbolAddress((void**)&gx, g_X);

    dim3 gemmGrid(DD / 128, MM / 128);   // (8, 64)
    gemm_tf32_nt_bias<<<gemmGrid, 256>>>(query, Wq, bq, gq);
    gemm_tf32_nt_bias<<<gemmGrid, 256>>>(key,   Wk, bk, gk);
    gemm_tf32_nt_bias<<<gemmGrid, 256>>>(value, Wv, bv, gv);

    dim3 attnGrid(SS / FBQ, HH, BB);     // (32, 16, 4)
    flash_tf32<<<attnGrid, 128>>>(gq, gk, gv, gx);

    gemm_tf32_nt_bias<<<gemmGrid, 256>>>(gx, Wo, bo, out);
}

// round 8
// speedup vs baseline: 1.6061x; 1.1209x over previous
#include <cuda_runtime.h>
#include <cstdint>
#include <math.h>
#include <stddef.h>

// Problem shape (fixed)
#define BB 4
#define SS 2048
#define DD 1024
#define HH 16
#define HD 64
#define MM (BB * SS)   // 8192 rows for all projection GEMMs

// ---------------------------------------------------------------------------
// Scratch (__device__ globals; no runtime allocation allowed)
// ---------------------------------------------------------------------------
__device__ float g_Q[MM * DD];
__device__ float g_K[MM * DD];
__device__ float g_V[MM * DD];
__device__ float g_X[MM * DD];

// ---------------------------------------------------------------------------
// tf32 / mma / ldmatrix helpers
// ---------------------------------------------------------------------------
__device__ __forceinline__ uint32_t f2tf32(float x) {
    uint32_t r;
    asm("cvt.rna.tf32.f32 %0, %1;" : "=r"(r) : "f"(x));
    return r;
}
__device__ __forceinline__ float tf32f(float x) {
    return __uint_as_float(f2tf32(x));
}
__device__ __forceinline__ void mma_tf32(float c[4],
    uint32_t a0, uint32_t a1, uint32_t a2, uint32_t a3,
    uint32_t b0, uint32_t b1)
{
    asm volatile(
        "mma.sync.aligned.m16n8k8.row.col.f32.tf32.tf32.f32 "
        "{%0,%1,%2,%3}, {%4,%5,%6,%7}, {%8,%9}, {%0,%1,%2,%3};"
        : "+f"(c[0]), "+f"(c[1]), "+f"(c[2]), "+f"(c[3])
        : "r"(a0), "r"(a1), "r"(a2), "r"(a3), "r"(b0), "r"(b1));
}
// ldmatrix x4: each matrix = 8 rows x 16 bytes (= 8x4 fp32). Lane l supplies
// the row address for matrix (l>>3), row (l&7). Output reg d_i on lane l is
// matrix i element [row = l>>2][word = l&3].
__device__ __forceinline__ void ldm_x4(uint32_t& d0, uint32_t& d1,
                                       uint32_t& d2, uint32_t& d3,
                                       const float* p)
{
    uint32_t addr = (uint32_t)__cvta_generic_to_shared(p);
    asm volatile("ldmatrix.sync.aligned.m8n8.x4.shared.b16 {%0,%1,%2,%3}, [%4];"
        : "=r"(d0), "=r"(d1), "=r"(d2), "=r"(d3) : "r"(addr));
}

// ---------------------------------------------------------------------------
// GEMM (3xTF32): C[M,N] = A[M,K] * W[N,K]^T + bias[N],  M=8192, N=K=1024.
// 128x128 block tile, BK=16, 256 threads (8 warps, warp tile 64x32).
// SMEM tiles row-major [m][k] / [n][k], stride 20 floats (conflict-free
// ldmatrix). Register prefetch of the next k-slab. 3-term tf32 split.
// ---------------------------------------------------------------------------
#define GKP 20   // SMEM row stride in floats (rows cover all 32 banks)

__global__ void __launch_bounds__(256, 2) gemm_tf32_nt_bias(
    const float* __restrict__ A, const float* __restrict__ W,
    const float* __restrict__ bias, float* __restrict__ C)
{
    __shared__ __align__(16) float Ah[128][GKP], Al[128][GKP];
    __shared__ __align__(16) float Bh[128][GKP], Bl[128][GKP];

    const int tid  = threadIdx.x;
    const int lane = tid & 31;
    const int wid  = tid >> 5;
    const int cl   = lane & 3;    // 0..3 (k quad within frag)
    const int wm   = (wid & 1) * 64;
    const int wn   = (wid >> 1) * 32;
    // ldmatrix addressing helpers
    const int mrow = lane & 7;
    const int msel = (lane >> 3) & 1;
    const int mhi  = lane >> 4;

    const int row0 = blockIdx.y * 128;
    const int col0 = blockIdx.x * 128;

    // Loader mapping: 512 float4 per operand per k-slab; 2 per thread.
    // f4 index i -> row = i>>2, kc = (i&3)*4
    const int rA0 = tid >> 2,         kA0 = (tid & 3) * 4;
    const int rA1 = (tid + 256) >> 2, kA1 = ((tid + 256) & 3) * 4;

    float c[4][4][4];
#pragma unroll
    for (int mt = 0; mt < 4; mt++)
#pragma unroll
        for (int nt = 0; nt < 4; nt++)
#pragma unroll
            for (int q = 0; q < 4; q++) c[mt][nt][q] = 0.0f;

    float4 pa0, pa1, pb0, pb1;
    pa0 = *(const float4*)(A + (size_t)(row0 + rA0) * 1024 + kA0);
    pa1 = *(const float4*)(A + (size_t)(row0 + rA1) * 1024 + kA1);
    pb0 = *(const float4*)(W + (size_t)(col0 + rA0) * 1024 + kA0);
    pb1 = *(const float4*)(W + (size_t)(col0 + rA1) * 1024 + kA1);

    for (int k0 = 0; k0 < 1024; k0 += 16) {
        // split + store current slab (row-major, h/l)
        {
            const float* va[2] = {(const float*)&pa0, (const float*)&pa1};
            const float* vb[2] = {(const float*)&pb0, (const float*)&pb1};
            const int rr[2] = {rA0, rA1};
            const int kk[2] = {kA0, kA1};
#pragma unroll
            for (int u = 0; u < 2; u++) {
                float4 h4, l4, g4, m4;
                float h;
                h = tf32f(va[u][0]); h4.x = h; l4.x = tf32f(va[u][0] - h);
                h = tf32f(va[u][1]); h4.y = h; l4.y = tf32f(va[u][1] - h);
                h = tf32f(va[u][2]); h4.z = h; l4.z = tf32f(va[u][2] - h);
                h = tf32f(va[u][3]); h4.w = h; l4.w = tf32f(va[u][3] - h);
                *(float4*)&Ah[rr[u]][kk[u]] = h4;
                *(float4*)&Al[rr[u]][kk[u]] = l4;
                h = tf32f(vb[u][0]); g4.x = h; m4.x = tf32f(vb[u][0] - h);
                h = tf32f(vb[u][1]); g4.y = h; m4.y = tf32f(vb[u][1] - h);
                h = tf32f(vb[u][2]); g4.z = h; m4.z = tf32f(vb[u][2] - h);
                h = tf32f(vb[u][3]); g4.w = h; m4.w = tf32f(vb[u][3] - h);
                *(float4*)&Bh[rr[u]][kk[u]] = g4;
                *(float4*)&Bl[rr[u]][kk[u]] = m4;
            }
        }
        __syncthreads();

        const bool more = (k0 + 16) < 1024;
        if (more) {
            const int kn = k0 + 16;
            pa0 = *(const float4*)(A + (size_t)(row0 + rA0) * 1024 + kn + kA0);
            pa1 = *(const float4*)(A + (size_t)(row0 + rA1) * 1024 + kn + kA1);
            pb0 = *(const float4*)(W + (size_t)(col0 + rA0) * 1024 + kn + kA0);
            pb1 = *(const float4*)(W + (size_t)(col0 + rA1) * 1024 + kn + kA1);
        }

#pragma unroll
        for (int kk8 = 0; kk8 < 2; kk8++) {
            const int kb = kk8 * 8;
            // B fragments: b_h0[nt] (k-lo reg), b_h1[nt] (k-hi reg)
            uint32_t b_h0[4], b_h1[4], b_l0[4], b_l1[4];
            ldm_x4(b_h0[0], b_h1[0], b_h0[1], b_h1[1],
                   &Bh[wn + (0 + mhi) * 8 + mrow][kb + msel * 4]);
            ldm_x4(b_h0[2], b_h1[2], b_h0[3], b_h1[3],
                   &Bh[wn + (2 + mhi) * 8 + mrow][kb + msel * 4]);
            ldm_x4(b_l0[0], b_l1[0], b_l0[1], b_l1[1],
                   &Bl[wn + (0 + mhi) * 8 + mrow][kb + msel * 4]);
            ldm_x4(b_l0[2], b_l1[2], b_l0[3], b_l1[3],
                   &Bl[wn + (2 + mhi) * 8 + mrow][kb + msel * 4]);
#pragma unroll
            for (int mt = 0; mt < 4; mt++) {
                uint32_t ah[4], al[4];
                ldm_x4(ah[0], ah[1], ah[2], ah[3],
                       &Ah[wm + mt * 16 + msel * 8 + mrow][kb + mhi * 4]);
                ldm_x4(al[0], al[1], al[2], al[3],
                       &Al[wm + mt * 16 + msel * 8 + mrow][kb + mhi * 4]);
#pragma unroll
                for (int nt = 0; nt < 4; nt++) {
                    mma_tf32(c[mt][nt], ah[0], ah[1], ah[2], ah[3], b_h0[nt], b_h1[nt]);
                    mma_tf32(c[mt][nt], ah[0], ah[1], ah[2], ah[3], b_l0[nt], b_l1[nt]);
                    mma_tf32(c[mt][nt], al[0], al[1], al[2], al[3], b_h0[nt], b_h1[nt]);
                }
            }
        }
        __syncthreads();
    }

    // Epilogue: add bias, write fp32
    const int r = lane >> 2;
#pragma unroll
    for (int mt = 0; mt < 4; mt++) {
        const int gr0 = row0 + wm + mt * 16 + r;
        const int gr1 = gr0 + 8;
#pragma unroll
        for (int nt = 0; nt < 4; nt++) {
            const int gc = col0 + wn + nt * 8 + 2 * cl;
            const float b0 = __ldg(bias + gc);
            const float b1 = __ldg(bias + gc + 1);
            float2 v0 = {c[mt][nt][0] + b0, c[mt][nt][1] + b1};
            float2 v1 = {c[mt][nt][2] + b0, c[mt][nt][3] + b1};
            *(float2*)(C + (size_t)gr0 * 1024 + gc) = v0;
            *(float2*)(C + (size_t)gr1 * 1024 + gc) = v1;
        }
    }
}

// ---------------------------------------------------------------------------
// Flash attention, tensor-core tf32 with ldmatrix fragment loads.
// Block = (b, h, 64-query tile); 128 threads = 4 warps; warp owns 16 q rows.
// KV tile = 32 keys. QK^T: 1xTF32 (1/32 scale folded into Q).
// PV: 3-term split. Layouts: Ksm[key][dim], V transposed [dim][key], P[q][key].
// ---------------------------------------------------------------------------
#define FBQ 64
#define FBKV 32

__global__ void __launch_bounds__(128, 4) flash_tf32(
    const float* __restrict__ Q, const float* __restrict__ K,
    const float* __restrict__ V, float* __restrict__ O)
{
    __shared__ __align__(16) float Ksm[FBKV][68];      // [key][dim]
    __shared__ __align__(16) float Vh[HD][36], Vl[HD][36];   // [dim][key]
    __shared__ __align__(16) float Ph[FBQ][36], Pl[FBQ][36]; // [q][key]

    const int b  = blockIdx.z;
    const int h  = blockIdx.y;
    const int q0 = blockIdx.x * FBQ;

    const int tid  = threadIdx.x;
    const int lane = tid & 31;
    const int wid  = tid >> 5;
    const int r    = lane >> 2;
    const int cl   = lane & 3;
    const int qw   = wid * 16;
    const int mrow = lane & 7;
    const int msel = (lane >> 3) & 1;
    const int mhi  = lane >> 4;

    // ---- Q fragments, pre-scaled by 1/32, tf32-rounded, in registers
    uint32_t qa[8][4];
    {
        const size_t base = ((size_t)(b * SS + q0 + qw + r)) * DD + (size_t)h * HD;
#pragma unroll
        for (int c = 0; c < 8; c++) {
            const size_t p0 = base + c * 8 + cl;
            qa[c][0] = f2tf32(Q[p0] * 0.03125f);
            qa[c][1] = f2tf32(Q[p0 + (size_t)8 * DD] * 0.03125f);
            qa[c][2] = f2tf32(Q[p0 + 4] * 0.03125f);
            qa[c][3] = f2tf32(Q[p0 + (size_t)8 * DD + 4] * 0.03125f);
        }
    }

    float o[8][4];
#pragma unroll
    for (int dn = 0; dn < 8; dn++)
#pragma unroll
        for (int q = 0; q < 4; q++) o[dn][q] = 0.0f;
    float m0 = -1e30f, m1 = -1e30f, l0 = 0.0f, l1 = 0.0f;

    // V loader mapping (register transpose): thread handles 4 dims x 4 keys
    const int vdd = tid >> 3;  // dim block 0..15
    const int vkk = tid & 7;   // key block 0..7

    for (int kv = 0; kv < SS; kv += FBKV) {
        __syncthreads();   // prior tile fully consumed

        // ---- K tile: [key][dim], tf32-rounded
        for (int i = tid; i < FBKV * (HD / 4); i += 128) {
            const int key = i >> 4;
            const int c4  = (i & 15) * 4;
            const size_t g = ((size_t)(b * SS + kv + key)) * DD + (size_t)h * HD + c4;
            float4 kk = *(const float4*)(K + g);
            float4 kh = {tf32f(kk.x), tf32f(kk.y), tf32f(kk.z), tf32f(kk.w)};
            *(float4*)&Ksm[key][c4] = kh;
        }
        // ---- V tile: transpose to [dim][key], split h/l
        {
            const size_t gv = ((size_t)(b * SS + kv + 4 * vkk)) * DD + (size_t)h * HD + 4 * vdd;
            float4 r0 = *(const float4*)(V + gv);
            float4 r1 = *(const float4*)(V + gv + DD);
            float4 r2 = *(const float4*)(V + gv + 2 * DD);
            float4 r3 = *(const float4*)(V + gv + 3 * DD);
            const float vt[4][4] = {
                {r0.x, r1.x, r2.x, r3.x}, {r0.y, r1.y, r2.y, r3.y},
                {r0.z, r1.z, r2.z, r3.z}, {r0.w, r1.w, r2.w, r3.w}};
#pragma unroll
            for (int t = 0; t < 4; t++) {
                float4 h4, l4;
                float hh;
                hh = tf32f(vt[t][0]); h4.x = hh; l4.x = tf32f(vt[t][0] - hh);
                hh = tf32f(vt[t][1]); h4.y = hh; l4.y = tf32f(vt[t][1] - hh);
                hh = tf32f(vt[t][2]); h4.z = hh; l4.z = tf32f(vt[t][2] - hh);
                hh = tf32f(vt[t][3]); h4.w = hh; l4.w = tf32f(vt[t][3] - hh);
                *(float4*)&Vh[4 * vdd + t][4 * vkk] = h4;
                *(float4*)&Vl[4 * vdd + t][4 * vkk] = l4;
            }
        }
        __syncthreads();

        // ---- S = Q K^T ----
        float s[4][4];
#pragma unroll
        for (int nt = 0; nt < 4; nt++)
#pragma unroll
            for (int q = 0; q < 4; q++) s[nt][q] = 0.0f;
#pragma unroll
        for (int c = 0; c < 8; c++) {
            uint32_t kb0[4], kb1[4];
            ldm_x4(kb0[0], kb1[0], kb0[1], kb1[1],
                   &Ksm[(0 + mhi) * 8 + mrow][c * 8 + msel * 4]);
            ldm_x4(kb0[2], kb1[2], kb0[3], kb1[3],
                   &Ksm[(2 + mhi) * 8 + mrow][c * 8 + msel * 4]);
#pragma unroll
            for (int nt = 0; nt < 4; nt++)
                mma_tf32(s[nt], qa[c][0], qa[c][1], qa[c][2], qa[c][3], kb0[nt], kb1[nt]);
        }

        // ---- online softmax; split P to SMEM ----
        {
            float tm = fmaxf(fmaxf(s[0][0], s[0][1]), fmaxf(s[1][0], s[1][1]));
            tm = fmaxf(tm, fmaxf(fmaxf(s[2][0], s[2][1]), fmaxf(s[3][0], s[3][1])));
            tm = fmaxf(tm, __shfl_xor_sync(0xffffffffu, tm, 1));
            tm = fmaxf(tm, __shfl_xor_sync(0xffffffffu, tm, 2));
            const float mnew = fmaxf(m0, tm);
            const float corr = __expf(m0 - mnew);
            m0 = mnew;
            float rs = 0.0f;
#pragma unroll
            for (int nt = 0; nt < 4; nt++) {
                const float p0 = __expf(s[nt][0] - mnew);
                const float p1 = __expf(s[nt][1] - mnew);
                rs += p0 + p1;
                const float h0 = tf32f(p0), h1 = tf32f(p1);
                float2 ph = {h0, h1};
                float2 pl = {tf32f(p0 - h0), tf32f(p1 - h1)};
                *(float2*)&Ph[qw + r][nt * 8 + 2 * cl] = ph;
                *(float2*)&Pl[qw + r][nt * 8 + 2 * cl] = pl;
            }
            rs += __shfl_xor_sync(0xffffffffu, rs, 1);
            rs += __shfl_xor_sync(0xffffffffu, rs, 2);
            l0 = l0 * corr + rs;
#pragma unroll
            for (int dn = 0; dn < 8; dn++) { o[dn][0] *= corr; o[dn][1] *= corr; }
        }
        {
            float tm = fmaxf(fmaxf(s[0][2], s[0][3]), fmaxf(s[1][2], s[1][3]));
            tm = fmaxf(tm, fmaxf(fmaxf(s[2][2], s[2][3]), fmaxf(s[3][2], s[3][3])));
            tm = fmaxf(tm, __shfl_xor_sync(0xffffffffu, tm, 1));
            tm = fmaxf(tm, __shfl_xor_sync(0xffffffffu, tm, 2));
            const float mnew = fmaxf(m1, tm);
            const float corr = __expf(m1 - mnew);
            m1 = mnew;
            float rs = 0.0f;
#pragma unroll
            for (int nt = 0; nt < 4; nt++) {
                const float p0 = __expf(s[nt][2] - mnew);
                const float p1 = __expf(s[nt][3] - mnew);
                rs += p0 + p1;
                const float h0 = tf32f(p0), h1 = tf32f(p1);
                float2 ph = {h0, h1};
                float2 pl = {tf32f(p0 - h0), tf32f(p1 - h1)};
                *(float2*)&Ph[qw + r + 8][nt * 8 + 2 * cl] = ph;
                *(float2*)&Pl[qw + r + 8][nt * 8 + 2 * cl] = pl;
            }
            rs += __shfl_xor_sync(0xffffffffu, rs, 1);
            rs += __shfl_xor_sync(0xffffffffu, rs, 2);
            l1 = l1 * corr + rs;
#pragma unroll
            for (int dn = 0; dn < 8; dn++) { o[dn][2] *= corr; o[dn][3] *= corr; }
        }
        __syncwarp();   // P rows are warp-private: produce -> consume in-warp

        // ---- O += P V (3-term split) ----
#pragma unroll
        for (int kc = 0; kc < 4; kc++) {
            uint32_t pah[4], pal[4];
            ldm_x4(pah[0], pah[1], pah[2], pah[3],
                   &Ph[qw + msel * 8 + mrow][kc * 8 + mhi * 4]);
            ldm_x4(pal[0], pal[1], pal[2], pal[3],
                   &Pl[qw + msel * 8 + mrow][kc * 8 + mhi * 4]);
#pragma unroll
            for (int dnb = 0; dnb < 8; dnb += 2) {
                uint32_t vh0[2], vh1[2], vl0[2], vl1[2];
                ldm_x4(vh0[0], vh1[0], vh0[1], vh1[1],
                       &Vh[(dnb + mhi) * 8 + mrow][kc * 8 + msel * 4]);
                ldm_x4(vl0[0], vl1[0], vl0[1], vl1[1],
                       &Vl[(dnb + mhi) * 8 + mrow][kc * 8 + msel * 4]);
#pragma unroll
                for (int j = 0; j < 2; j++) {
                    const int dn = dnb + j;
                    mma_tf32(o[dn], pah[0], pah[1], pah[2], pah[3], vh0[j], vh1[j]);
                    mma_tf32(o[dn], pah[0], pah[1], pah[2], pah[3], vl0[j], vl1[j]);
                    mma_tf32(o[dn], pal[0], pal[1], pal[2], pal[3], vh0[j], vh1[j]);
                }
            }
        }
    }

    // ---- epilogue: normalize, write [B,S,D] heads re-interleaved ----
    const float inv0 = 1.0f / l0;
    const float inv1 = 1.0f / l1;
    const size_t ob0 = ((size_t)(b * SS + q0 + qw + r)) * DD + (size_t)h * HD;
    const size_t ob1 = ob0 + (size_t)8 * DD;
#pragma unroll
    for (int dn = 0; dn < 8; dn++) {
        const int gc = dn * 8 + 2 * cl;
        float2 v0 = {o[dn][0] * inv0, o[dn][1] * inv0};
        float2 v1 = {o[dn][2] * inv1, o[dn][3] * inv1};
        *(float2*)(O + ob0 + gc) = v0;
        *(float2*)(O + ob1 + gc) = v1;
    }
}

// ---------------------------------------------------------------------------
// Launch: 3 projection GEMMs -> flash attention -> output GEMM.
// ---------------------------------------------------------------------------
extern "C" void kernel_launch(void* const* d_in, const int* in_sizes, int n_in,
                              void* d_out, int out_size)
{
    const float* query = (const float*)d_in[0];
    const float* key   = (const float*)d_in[1];
    const float* value = (const float*)d_in[2];
    const float* Wq    = (const float*)d_in[3];
    const float* bq    = (const float*)d_in[4];
    const float* Wk    = (const float*)d_in[5];
    const float* bk    = (const float*)d_in[6];
    const float* Wv    = (const float*)d_in[7];
    const float* bv    = (const float*)d_in[8];
    const float* Wo    = (const float*)d_in[9];
    const float* bo    = (const float*)d_in[10];
    float* out = (float*)d_out;

    float *gq, *gk, *gv, *gx;
    cudaGetSymbolAddress((void**)&gq, g_Q);
    cudaGetSymbolAddress((void**)&gk, g_K);
    cudaGetSymbolAddress((void**)&gv, g_V);
    cudaGetSymbolAddress((void**)&gx, g_X);

    dim3 gemmGrid(DD / 128, MM / 128);   // (8, 64)
    gemm_tf32_nt_bias<<<gemmGrid, 256>>>(query, Wq, bq, gq);
    gemm_tf32_nt_bias<<<gemmGrid, 256>>>(key,   Wk, bk, gk);
    gemm_tf32_nt_bias<<<gemmGrid, 256>>>(value, Wv, bv, gv);

    dim3 attnGrid(SS / FBQ, HH, BB);     // (32, 16, 4)
    flash_tf32<<<attnGrid, 128>>>(gq, gk, gv, gx);

    gemm_tf32_nt_bias<<<gemmGrid, 256>>>(gx, Wo, bo, out);
}

// round 12
// speedup vs baseline: 2.0719x; 1.2901x over previous
#include <cuda_runtime.h>
#include <cstdint>
#include <math.h>
#include <stddef.h>

// Problem shape (fixed)
#define BB 4
#define SS 2048
#define DD 1024
#define HH 16
#define HD 64
#define MM (BB * SS)   // 8192 rows for all projection GEMMs

// ---------------------------------------------------------------------------
// Scratch (__device__ globals; no runtime allocation allowed)
// ---------------------------------------------------------------------------
__device__ float g_Q[MM * DD];
__device__ float g_K[MM * DD];
__device__ float g_V[MM * DD];
__device__ float g_X[MM * DD];

// ---------------------------------------------------------------------------
// tf32 / mma / ldmatrix helpers
// ---------------------------------------------------------------------------
__device__ __forceinline__ uint32_t f2tf32(float x) {
    uint32_t r;
    asm("cvt.rna.tf32.f32 %0, %1;" : "=r"(r) : "f"(x));
    return r;
}
__device__ __forceinline__ float tf32f(float x) {
    return __uint_as_float(f2tf32(x));
}
__device__ __forceinline__ void mma_tf32(float c[4],
    uint32_t a0, uint32_t a1, uint32_t a2, uint32_t a3,
    uint32_t b0, uint32_t b1)
{
    asm volatile(
        "mma.sync.aligned.m16n8k8.row.col.f32.tf32.tf32.f32 "
        "{%0,%1,%2,%3}, {%4,%5,%6,%7}, {%8,%9}, {%0,%1,%2,%3};"
        : "+f"(c[0]), "+f"(c[1]), "+f"(c[2]), "+f"(c[3])
        : "r"(a0), "r"(a1), "r"(a2), "r"(a3), "r"(b0), "r"(b1));
}
// ldmatrix x4: each matrix = 8 rows x 16 bytes (= 8x4 fp32). Lane l supplies
// the row address for matrix (l>>3), row (l&7). Output reg d_i on lane l is
// matrix i element [row = l>>2][word = l&3].
__device__ __forceinline__ void ldm_x4(uint32_t& d0, uint32_t& d1,
                                       uint32_t& d2, uint32_t& d3,
                                       const float* p)
{
    uint32_t addr = (uint32_t)__cvta_generic_to_shared(p);
    asm volatile("ldmatrix.sync.aligned.m8n8.x4.shared.b16 {%0,%1,%2,%3}, [%4];"
        : "=r"(d0), "=r"(d1), "=r"(d2), "=r"(d3) : "r"(addr));
}

// ---------------------------------------------------------------------------
// GEMM (3xTF32): C[M,N] = A[M,K] * W[N,K]^T + bias[N],  M=8192, N=K=1024.
// (unchanged from the verified round-8 kernel)
// ---------------------------------------------------------------------------
#define GKP 20   // SMEM row stride in floats (rows cover all 32 banks)

__global__ void __launch_bounds__(256, 2) gemm_tf32_nt_bias(
    const float* __restrict__ A, const float* __restrict__ W,
    const float* __restrict__ bias, float* __restrict__ C)
{
    __shared__ __align__(16) float Ah[128][GKP], Al[128][GKP];
    __shared__ __align__(16) float Bh[128][GKP], Bl[128][GKP];

    const int tid  = threadIdx.x;
    const int lane = tid & 31;
    const int wid  = tid >> 5;
    const int cl   = lane & 3;
    const int wm   = (wid & 1) * 64;
    const int wn   = (wid >> 1) * 32;
    const int mrow = lane & 7;
    const int msel = (lane >> 3) & 1;
    const int mhi  = lane >> 4;

    const int row0 = blockIdx.y * 128;
    const int col0 = blockIdx.x * 128;

    const int rA0 = tid >> 2,         kA0 = (tid & 3) * 4;
    const int rA1 = (tid + 256) >> 2, kA1 = ((tid + 256) & 3) * 4;

    float c[4][4][4];
#pragma unroll
    for (int mt = 0; mt < 4; mt++)
#pragma unroll
        for (int nt = 0; nt < 4; nt++)
#pragma unroll
            for (int q = 0; q < 4; q++) c[mt][nt][q] = 0.0f;

    float4 pa0, pa1, pb0, pb1;
    pa0 = *(const float4*)(A + (size_t)(row0 + rA0) * 1024 + kA0);
    pa1 = *(const float4*)(A + (size_t)(row0 + rA1) * 1024 + kA1);
    pb0 = *(const float4*)(W + (size_t)(col0 + rA0) * 1024 + kA0);
    pb1 = *(const float4*)(W + (size_t)(col0 + rA1) * 1024 + kA1);

    for (int k0 = 0; k0 < 1024; k0 += 16) {
        {
            const float* va[2] = {(const float*)&pa0, (const float*)&pa1};
            const float* vb[2] = {(const float*)&pb0, (const float*)&pb1};
            const int rr[2] = {rA0, rA1};
            const int kk[2] = {kA0, kA1};
#pragma unroll
            for (int u = 0; u < 2; u++) {
                float4 h4, l4, g4, m4;
                float h;
                h = tf32f(va[u][0]); h4.x = h; l4.x = tf32f(va[u][0] - h);
                h = tf32f(va[u][1]); h4.y = h; l4.y = tf32f(va[u][1] - h);
                h = tf32f(va[u][2]); h4.z = h; l4.z = tf32f(va[u][2] - h);
                h = tf32f(va[u][3]); h4.w = h; l4.w = tf32f(va[u][3] - h);
                *(float4*)&Ah[rr[u]][kk[u]] = h4;
                *(float4*)&Al[rr[u]][kk[u]] = l4;
                h = tf32f(vb[u][0]); g4.x = h; m4.x = tf32f(vb[u][0] - h);
                h = tf32f(vb[u][1]); g4.y = h; m4.y = tf32f(vb[u][1] - h);
                h = tf32f(vb[u][2]); g4.z = h; m4.z = tf32f(vb[u][2] - h);
                h = tf32f(vb[u][3]); g4.w = h; m4.w = tf32f(vb[u][3] - h);
                *(float4*)&Bh[rr[u]][kk[u]] = g4;
                *(float4*)&Bl[rr[u]][kk[u]] = m4;
            }
        }
        __syncthreads();

        const bool more = (k0 + 16) < 1024;
        if (more) {
            const int kn = k0 + 16;
            pa0 = *(const float4*)(A + (size_t)(row0 + rA0) * 1024 + kn + kA0);
            pa1 = *(const float4*)(A + (size_t)(row0 + rA1) * 1024 + kn + kA1);
            pb0 = *(const float4*)(W + (size_t)(col0 + rA0) * 1024 + kn + kA0);
            pb1 = *(const float4*)(W + (size_t)(col0 + rA1) * 1024 + kn + kA1);
        }

#pragma unroll
        for (int kk8 = 0; kk8 < 2; kk8++) {
            const int kb = kk8 * 8;
            uint32_t b_h0[4], b_h1[4], b_l0[4], b_l1[4];
            ldm_x4(b_h0[0], b_h1[0], b_h0[1], b_h1[1],
                   &Bh[wn + (0 + mhi) * 8 + mrow][kb + msel * 4]);
            ldm_x4(b_h0[2], b_h1[2], b_h0[3], b_h1[3],
                   &Bh[wn + (2 + mhi) * 8 + mrow][kb + msel * 4]);
            ldm_x4(b_l0[0], b_l1[0], b_l0[1], b_l1[1],
                   &Bl[wn + (0 + mhi) * 8 + mrow][kb + msel * 4]);
            ldm_x4(b_l0[2], b_l1[2], b_l0[3], b_l1[3],
                   &Bl[wn + (2 + mhi) * 8 + mrow][kb + msel * 4]);
#pragma unroll
            for (int mt = 0; mt < 4; mt++) {
                uint32_t ah[4], al[4];
                ldm_x4(ah[0], ah[1], ah[2], ah[3],
                       &Ah[wm + mt * 16 + msel * 8 + mrow][kb + mhi * 4]);
                ldm_x4(al[0], al[1], al[2], al[3],
                       &Al[wm + mt * 16 + msel * 8 + mrow][kb + mhi * 4]);
#pragma unroll
                for (int nt = 0; nt < 4; nt++) {
                    mma_tf32(c[mt][nt], ah[0], ah[1], ah[2], ah[3], b_h0[nt], b_h1[nt]);
                    mma_tf32(c[mt][nt], ah[0], ah[1], ah[2], ah[3], b_l0[nt], b_l1[nt]);
                    mma_tf32(c[mt][nt], al[0], al[1], al[2], al[3], b_h0[nt], b_h1[nt]);
                }
            }
        }
        __syncthreads();
    }

    const int r = lane >> 2;
#pragma unroll
    for (int mt = 0; mt < 4; mt++) {
        const int gr0 = row0 + wm + mt * 16 + r;
        const int gr1 = gr0 + 8;
#pragma unroll
        for (int nt = 0; nt < 4; nt++) {
            const int gc = col0 + wn + nt * 8 + 2 * cl;
            const float b0 = __ldg(bias + gc);
            const float b1 = __ldg(bias + gc + 1);
            float2 v0 = {c[mt][nt][0] + b0, c[mt][nt][1] + b1};
            float2 v1 = {c[mt][nt][2] + b0, c[mt][nt][3] + b1};
            *(float2*)(C + (size_t)gr0 * 1024 + gc) = v0;
            *(float2*)(C + (size_t)gr1 * 1024 + gc) = v1;
        }
    }
}

// ---------------------------------------------------------------------------
// Flash attention, tensor-core tf32, ldmatrix loads, prefetch pipeline.
// Block = (b, h, 128-query tile); 256 threads = 8 warps; warp owns 16 q rows.
// KV tile = 32 keys, register-prefetched (global loads overlap compute).
// QK^T: 1xTF32 (1/32 folded into Q). PV: 2-term split (Ph*Vh + Ph*Vl).
// ---------------------------------------------------------------------------
#define FBQ 128
#define FBKV 32

__global__ void __launch_bounds__(256, 2) flash_tf32(
    const float* __restrict__ Q, const float* __restrict__ K,
    const float* __restrict__ V, float* __restrict__ O)
{
    __shared__ __align__(16) float Ksm[FBKV][68];            // [key][dim]
    __shared__ __align__(16) float Vh[HD][36], Vl[HD][36];   // [dim][key]
    __shared__ __align__(16) float Ph[FBQ][36];              // [q][key]

    const int b  = blockIdx.z;
    const int h  = blockIdx.y;
    const int q0 = blockIdx.x * FBQ;

    const int tid  = threadIdx.x;
    const int lane = tid & 31;
    const int wid  = tid >> 5;          // 0..7
    const int r    = lane >> 2;
    const int cl   = lane & 3;
    const int qw   = wid * 16;
    const int mrow = lane & 7;
    const int msel = (lane >> 3) & 1;
    const int mhi  = lane >> 4;

    // ---- Q fragments, pre-scaled by 1/32, tf32-rounded, in registers
    uint32_t qa[8][4];
    {
        const size_t base = ((size_t)(b * SS + q0 + qw + r)) * DD + (size_t)h * HD;
#pragma unroll
        for (int c = 0; c < 8; c++) {
            const size_t p0 = base + c * 8 + cl;
            qa[c][0] = f2tf32(Q[p0] * 0.03125f);
            qa[c][1] = f2tf32(Q[p0 + (size_t)8 * DD] * 0.03125f);
            qa[c][2] = f2tf32(Q[p0 + 4] * 0.03125f);
            qa[c][3] = f2tf32(Q[p0 + (size_t)8 * DD + 4] * 0.03125f);
        }
    }

    float o[8][4];
#pragma unroll
    for (int dn = 0; dn < 8; dn++)
#pragma unroll
        for (int q = 0; q < 4; q++) o[dn][q] = 0.0f;
    float m0 = -1e30f, m1 = -1e30f, l0 = 0.0f, l1 = 0.0f;

    // Loader mappings (256 threads):
    // K: thread covers keys (tid>>4) and 16+(tid>>4) at dim quad (tid&15)*4.
    const int kKey = tid >> 4;           // 0..15
    const int kC4  = (tid & 15) * 4;     // 0..60
    // V: thread covers 4 dims x 2 keys (register transpose).
    const int vdd  = tid >> 4;           // dim block 0..15
    const int vk2  = tid & 15;           // key pair 0..15
    const size_t headOff = (size_t)h * HD;

    float4 pk0, pk1, pv0, pv1;
    // Prologue: load KV tile 0 into registers.
    {
        const size_t gk = ((size_t)(b * SS + kKey)) * DD + headOff + kC4;
        pk0 = *(const float4*)(K + gk);
        pk1 = *(const float4*)(K + gk + (size_t)16 * DD);
        const size_t gv = ((size_t)(b * SS + 2 * vk2)) * DD + headOff + 4 * vdd;
        pv0 = *(const float4*)(V + gv);
        pv1 = *(const float4*)(V + gv + DD);
    }

    for (int kv = 0; kv < SS; kv += FBKV) {
        // ---- retire prefetched tile into SMEM (convert/split/transpose) ----
        {
            float4 kh;
            kh.x = tf32f(pk0.x); kh.y = tf32f(pk0.y);
            kh.z = tf32f(pk0.z); kh.w = tf32f(pk0.w);
            *(float4*)&Ksm[kKey][kC4] = kh;
            kh.x = tf32f(pk1.x); kh.y = tf32f(pk1.y);
            kh.z = tf32f(pk1.z); kh.w = tf32f(pk1.w);
            *(float4*)&Ksm[kKey + 16][kC4] = kh;

            const float v0a[4] = {pv0.x, pv0.y, pv0.z, pv0.w};
            const float v1a[4] = {pv1.x, pv1.y, pv1.z, pv1.w};
#pragma unroll
            for (int t = 0; t < 4; t++) {
                const float h0 = tf32f(v0a[t]);
                const float h1 = tf32f(v1a[t]);
                float2 hv = {h0, h1};
                float2 lv = {tf32f(v0a[t] - h0), tf32f(v1a[t] - h1)};
                *(float2*)&Vh[4 * vdd + t][2 * vk2] = hv;
                *(float2*)&Vl[4 * vdd + t][2 * vk2] = lv;
            }
        }
        __syncthreads();

        // ---- issue next tile's global loads (latency overlapped) ----
        if (kv + FBKV < SS) {
            const int kn = kv + FBKV;
            const size_t gk = ((size_t)(b * SS + kn + kKey)) * DD + headOff + kC4;
            pk0 = *(const float4*)(K + gk);
            pk1 = *(const float4*)(K + gk + (size_t)16 * DD);
            const size_t gv = ((size_t)(b * SS + kn + 2 * vk2)) * DD + headOff + 4 * vdd;
            pv0 = *(const float4*)(V + gv);
            pv1 = *(const float4*)(V + gv + DD);
        }

        // ---- S = Q K^T ----
        float s[4][4];
#pragma unroll
        for (int nt = 0; nt < 4; nt++)
#pragma unroll
            for (int q = 0; q < 4; q++) s[nt][q] = 0.0f;
#pragma unroll
        for (int c = 0; c < 8; c++) {
            uint32_t kb0[4], kb1[4];
            ldm_x4(kb0[0], kb1[0], kb0[1], kb1[1],
                   &Ksm[(0 + mhi) * 8 + mrow][c * 8 + msel * 4]);
            ldm_x4(kb0[2], kb1[2], kb0[3], kb1[3],
                   &Ksm[(2 + mhi) * 8 + mrow][c * 8 + msel * 4]);
#pragma unroll
            for (int nt = 0; nt < 4; nt++)
                mma_tf32(s[nt], qa[c][0], qa[c][1], qa[c][2], qa[c][3], kb0[nt], kb1[nt]);
        }

        // ---- online softmax; store Ph ----
        {
            float tm = fmaxf(fmaxf(s[0][0], s[0][1]), fmaxf(s[1][0], s[1][1]));
            tm = fmaxf(tm, fmaxf(fmaxf(s[2][0], s[2][1]), fmaxf(s[3][0], s[3][1])));
            tm = fmaxf(tm, __shfl_xor_sync(0xffffffffu, tm, 1));
            tm = fmaxf(tm, __shfl_xor_sync(0xffffffffu, tm, 2));
            const float mnew = fmaxf(m0, tm);
            const float corr = __expf(m0 - mnew);
            m0 = mnew;
            float rs = 0.0f;
#pragma unroll
            for (int nt = 0; nt < 4; nt++) {
                const float p0 = __expf(s[nt][0] - mnew);
                const float p1 = __expf(s[nt][1] - mnew);
                rs += p0 + p1;
                float2 ph = {tf32f(p0), tf32f(p1)};
                *(float2*)&Ph[qw + r][nt * 8 + 2 * cl] = ph;
            }
            rs += __shfl_xor_sync(0xffffffffu, rs, 1);
            rs += __shfl_xor_sync(0xffffffffu, rs, 2);
            l0 = l0 * corr + rs;
#pragma unroll
            for (int dn = 0; dn < 8; dn++) { o[dn][0] *= corr; o[dn][1] *= corr; }
        }
        {
            float tm = fmaxf(fmaxf(s[0][2], s[0][3]), fmaxf(s[1][2], s[1][3]));
            tm = fmaxf(tm, fmaxf(fmaxf(s[2][2], s[2][3]), fmaxf(s[3][2], s[3][3])));
            tm = fmaxf(tm, __shfl_xor_sync(0xffffffffu, tm, 1));
            tm = fmaxf(tm, __shfl_xor_sync(0xffffffffu, tm, 2));
            const float mnew = fmaxf(m1, tm);
            const float corr = __expf(m1 - mnew);
            m1 = mnew;
            float rs = 0.0f;
#pragma unroll
            for (int nt = 0; nt < 4; nt++) {
                const float p0 = __expf(s[nt][2] - mnew);
                const float p1 = __expf(s[nt][3] - mnew);
                rs += p0 + p1;
                float2 ph = {tf32f(p0), tf32f(p1)};
                *(float2*)&Ph[qw + r + 8][nt * 8 + 2 * cl] = ph;
            }
            rs += __shfl_xor_sync(0xffffffffu, rs, 1);
            rs += __shfl_xor_sync(0xffffffffu, rs, 2);
            l1 = l1 * corr + rs;
#pragma unroll
            for (int dn = 0; dn < 8; dn++) { o[dn][2] *= corr; o[dn][3] *= corr; }
        }
        __syncwarp();   // Ph rows are warp-private: produce -> consume in-warp

        // ---- O += P V (2-term: Ph*Vh + Ph*Vl) ----
#pragma unroll
        for (int kc = 0; kc < 4; kc++) {
            uint32_t pah[4];
            ldm_x4(pah[0], pah[1], pah[2], pah[3],
                   &Ph[qw + msel * 8 + mrow][kc * 8 + mhi * 4]);
#pragma unroll
            for (int dnb = 0; dnb < 8; dnb += 2) {
                uint32_t vh0[2], vh1[2], vl0[2], vl1[2];
                ldm_x4(vh0[0], vh1[0], vh0[1], vh1[1],
                       &Vh[(dnb + mhi) * 8 + mrow][kc * 8 + msel * 4]);
                ldm_x4(vl0[0], vl1[0], vl0[1], vl1[1],
                       &Vl[(dnb + mhi) * 8 + mrow][kc * 8 + msel * 4]);
#pragma unroll
                for (int j = 0; j < 2; j++) {
                    const int dn = dnb + j;
                    mma_tf32(o[dn], pah[0], pah[1], pah[2], pah[3], vh0[j], vh1[j]);
                    mma_tf32(o[dn], pah[0], pah[1], pah[2], pah[3], vl0[j], vl1[j]);
                }
            }
        }
        __syncthreads();   // all reads of Ksm/Vh/Vl done before next retire
    }

    // ---- epilogue: normalize, write [B,S,D] heads re-interleaved ----
    const float inv0 = 1.0f / l0;
    const float inv1 = 1.0f / l1;
    const size_t ob0 = ((size_t)(b * SS + q0 + qw + r)) * DD + headOff;
    const size_t ob1 = ob0 + (size_t)8 * DD;
#pragma unroll
    for (int dn = 0; dn < 8; dn++) {
        const int gc = dn * 8 + 2 * cl;
        float2 v0 = {o[dn][0] * inv0, o[dn][1] * inv0};
        float2 v1 = {o[dn][2] * inv1, o[dn][3] * inv1};
        *(float2*)(O + ob0 + gc) = v0;
        *(float2*)(O + ob1 + gc) = v1;
    }
}

// ---------------------------------------------------------------------------
// Launch: 3 projection GEMMs -> flash attention -> output GEMM.
// ---------------------------------------------------------------------------
extern "C" void kernel_launch(void* const* d_in, const int* in_sizes, int n_in,
                              void* d_out, int out_size)
{
    const float* query = (const float*)d_in[0];
    const float* key   = (const float*)d_in[1];
    const float* value = (const float*)d_in[2];
    const float* Wq    = (const float*)d_in[3];
    const float* bq    = (const float*)d_in[4];
    const float* Wk    = (const float*)d_in[5];
    const float* bk    = (const float*)d_in[6];
    const float* Wv    = (const float*)d_in[7];
    const float* bv    = (const float*)d_in[8];
    const float* Wo    = (const float*)d_in[9];
    const float* bo    = (const float*)d_in[10];
    float* out = (float*)d_out;

    float *gq, *gk, *gv, *gx;
    cudaGetSymbolAddress((void**)&gq, g_Q);
    cudaGetSymbolAddress((void**)&gk, g_K);
    cudaGetSymbolAddress((void**)&gv, g_V);
    cudaGetSymbolAddress((void**)&gx, g_X);

    dim3 gemmGrid(DD / 128, MM / 128);   // (8, 64)
    gemm_tf32_nt_bias<<<gemmGrid, 256>>>(query, Wq, bq, gq);
    gemm_tf32_nt_bias<<<gemmGrid, 256>>>(key,   Wk, bk, gk);
    gemm_tf32_nt_bias<<<gemmGrid, 256>>>(value, Wv, bv, gv);

    dim3 attnGrid(SS / FBQ, HH, BB);     // (16, 16, 4)
    flash_tf32<<<attnGrid, 256>>>(gq, gk, gv, gx);

    gemm_tf32_nt_bias<<<gemmGrid, 256>>>(gx, Wo, bo, out);
}